// round 2
// baseline (speedup 1.0000x reference)
#include <cuda_runtime.h>
#include <cuda_bf16.h>
#include <math.h>
#include <stdint.h>

// Problem constants (fixed by setup_inputs)
#define N_ROWS 8192
#define DIM    256
#define TWO_N  16384
#define INV_TEMP 10.0f
#define NB 128          // number of 128-row tile blocks along each GEMM dim

// Scratch (no cudaMalloc allowed)
__device__ __align__(16) __nv_bfloat16 g_zb[(size_t)TWO_N * DIM];
__device__ float g_rowsum[TWO_N];
__device__ float g_acc[4];   // 0: sum of positive dots, 1: mse_price, 2: mse_change, 3: bce

// ---------------------------------------------------------------------------
__global__ void init_kernel() {
    int i = blockIdx.x * blockDim.x + threadIdx.x;
    if (i < TWO_N) g_rowsum[i] = 0.f;
    if (i < 4)     g_acc[i] = 0.f;
}

// ---------------------------------------------------------------------------
// One block per sample row: L2-normalize z1[r], z2[r]; write bf16 copies;
// accumulate exact fp32 positive-pair dot.
__global__ void norm_kernel(const float* __restrict__ z1, const float* __restrict__ z2) {
    int r = blockIdx.x;
    int t = threadIdx.x;           // 0..255 == DIM
    float a = z1[(size_t)r * DIM + t];
    float b = z2[(size_t)r * DIM + t];
    float sa = a * a, sb = b * b;
    #pragma unroll
    for (int o = 16; o > 0; o >>= 1) {
        sa += __shfl_xor_sync(0xffffffffu, sa, o);
        sb += __shfl_xor_sync(0xffffffffu, sb, o);
    }
    __shared__ float wsa[8], wsb[8], wsp[8];
    int w = t >> 5;
    if ((t & 31) == 0) { wsa[w] = sa; wsb[w] = sb; }
    __syncthreads();
    float ta = 0.f, tb = 0.f;
    #pragma unroll
    for (int i = 0; i < 8; i++) { ta += wsa[i]; tb += wsb[i]; }
    float inva = 1.f / fmaxf(sqrtf(ta), 1e-12f);
    float invb = 1.f / fmaxf(sqrtf(tb), 1e-12f);
    float an = a * inva, bn = b * invb;
    g_zb[(size_t)r * DIM + t]            = __float2bfloat16(an);
    g_zb[(size_t)(r + N_ROWS) * DIM + t] = __float2bfloat16(bn);
    float p = an * bn;
    #pragma unroll
    for (int o = 16; o > 0; o >>= 1) p += __shfl_xor_sync(0xffffffffu, p, o);
    if ((t & 31) == 0) wsp[w] = p;
    __syncthreads();
    if (t == 0) {
        float tp = 0.f;
        #pragma unroll
        for (int i = 0; i < 8; i++) tp += wsp[i];
        atomicAdd(&g_acc[0], tp);
    }
}

// ---------------------------------------------------------------------------
// Supervised losses: MSE(price), MSE(change), BCEWithLogits(criticality)
__global__ void sup_kernel(const float* __restrict__ pp, const float* __restrict__ pt,
                           const float* __restrict__ cp, const float* __restrict__ ct,
                           const float* __restrict__ xp, const float* __restrict__ xt) {
    int i = blockIdx.x * blockDim.x + threadIdx.x;
    float dp = pp[i] - pt[i];
    float dc = cp[i] - ct[i];
    float x = xp[i], tt = xt[i];
    float v1 = dp * dp;
    float v2 = dc * dc;
    float v3 = fmaxf(x, 0.f) - x * tt + log1pf(expf(-fabsf(x)));
    #pragma unroll
    for (int o = 16; o > 0; o >>= 1) {
        v1 += __shfl_xor_sync(0xffffffffu, v1, o);
        v2 += __shfl_xor_sync(0xffffffffu, v2, o);
        v3 += __shfl_xor_sync(0xffffffffu, v3, o);
    }
    __shared__ float s1[8], s2[8], s3[8];
    int w = threadIdx.x >> 5;
    if ((threadIdx.x & 31) == 0) { s1[w] = v1; s2[w] = v2; s3[w] = v3; }
    __syncthreads();
    if (threadIdx.x == 0) {
        float t1 = 0, t2 = 0, t3 = 0;
        #pragma unroll
        for (int k = 0; k < 8; k++) { t1 += s1[k]; t2 += s2[k]; t3 += s3[k]; }
        atomicAdd(&g_acc[1], t1);
        atomicAdd(&g_acc[2], t2);
        atomicAdd(&g_acc[3], t3);
    }
}

// ---------------------------------------------------------------------------
// Tiled bf16 MMA GEMM over the upper triangle of sim = Z Z^T, fused exp +
// row/col sum epilogue. 128x128 tile per CTA, K=256 in 4 chunks of 64.
// 8 warps: 4(m) x 2(n), each warp 32x64 via m16n8k16 mma.sync.
// Fragment loads via ldmatrix.x4 (LDSM) — 6 per k0-step vs 24 scalar LDS.
#define BK 64
#define LDS_PAD 72   // bf16 elements per smem row (64 + 8 pad; 144B pitch, 16B-aligned)

__device__ __forceinline__ void ldsm_x4(uint32_t& r0, uint32_t& r1,
                                        uint32_t& r2, uint32_t& r3, uint32_t addr) {
    asm volatile("ldmatrix.sync.aligned.m8n8.x4.shared.b16 {%0,%1,%2,%3}, [%4];\n"
                 : "=r"(r0), "=r"(r1), "=r"(r2), "=r"(r3) : "r"(addr));
}

__global__ void __launch_bounds__(256) gemm_exp_kernel() {
    int bi = blockIdx.y;
    int bj = blockIdx.x;
    if (bj < bi) return;   // upper triangle only

    __shared__ __align__(16) __nv_bfloat16 As[128][LDS_PAD];
    __shared__ __align__(16) __nv_bfloat16 Bs[128][LDS_PAD];

    int tid  = threadIdx.x;
    int warp = tid >> 5;
    int lane = tid & 31;
    int wm = (warp >> 1) * 32;   // 0,32,64,96
    int wn = (warp & 1) * 64;    // 0,64
    int g  = lane >> 2;          // 0..7
    int tg = lane & 3;           // 0..3

    float acc[2][8][4];
    #pragma unroll
    for (int m = 0; m < 2; m++)
        #pragma unroll
        for (int n = 0; n < 8; n++)
            #pragma unroll
            for (int k = 0; k < 4; k++) acc[m][n][k] = 0.f;

    const __nv_bfloat16* A = g_zb + (size_t)bi * 128 * DIM;
    const __nv_bfloat16* B = g_zb + (size_t)bj * 128 * DIM;

    int lr = tid >> 3;          // 0..31
    int lc = (tid & 7) * 8;     // 0..56 step 8

    // ldmatrix lane addressing (byte offsets; row pitch = 144B)
    uint32_t As_u32 = (uint32_t)__cvta_generic_to_shared(&As[0][0]);
    uint32_t Bs_u32 = (uint32_t)__cvta_generic_to_shared(&Bs[0][0]);
    // A: blocks (m-rows 0-7,k-lo)(8-15,k-lo)(0-7,k-hi)(8-15,k-hi)
    //    lanes 0-15 -> rows, lanes 16-31 -> k+8 halves
    uint32_t a_off[2];
    #pragma unroll
    for (int m = 0; m < 2; m++)
        a_off[m] = (uint32_t)((wm + m * 16 + (lane & 15)) * (LDS_PAD * 2)
                              + ((lane >> 4) * 8) * 2);
    // B: per x4 covers two 8-col n-tiles:
    //    lanes 0-7: n-lo rows,k-lo | 8-15: n-lo,k-hi | 16-23: n-hi,k-lo | 24-31: n-hi,k-hi
    uint32_t b_off[4];
    #pragma unroll
    for (int np = 0; np < 4; np++)
        b_off[np] = (uint32_t)((wn + np * 16 + ((lane >> 4) << 3) + (lane & 7)) * (LDS_PAD * 2)
                               + (((lane >> 3) & 1) * 8) * 2);

    for (int kt = 0; kt < DIM; kt += BK) {
        #pragma unroll
        for (int rr = 0; rr < 128; rr += 32) {
            *(uint4*)&As[lr + rr][lc] = *(const uint4*)&A[(size_t)(lr + rr) * DIM + kt + lc];
            *(uint4*)&Bs[lr + rr][lc] = *(const uint4*)&B[(size_t)(lr + rr) * DIM + kt + lc];
        }
        __syncthreads();

        #pragma unroll
        for (int k0 = 0; k0 < BK; k0 += 16) {
            uint32_t afr[2][4];
            uint32_t bfr[8][2];
            #pragma unroll
            for (int m = 0; m < 2; m++)
                ldsm_x4(afr[m][0], afr[m][1], afr[m][2], afr[m][3],
                        As_u32 + a_off[m] + (uint32_t)(k0 * 2));
            #pragma unroll
            for (int np = 0; np < 4; np++)
                ldsm_x4(bfr[2 * np][0], bfr[2 * np][1], bfr[2 * np + 1][0], bfr[2 * np + 1][1],
                        Bs_u32 + b_off[np] + (uint32_t)(k0 * 2));
            #pragma unroll
            for (int m = 0; m < 2; m++) {
                #pragma unroll
                for (int n = 0; n < 8; n++) {
                    asm volatile(
                        "mma.sync.aligned.m16n8k16.row.col.f32.bf16.bf16.f32 "
                        "{%0,%1,%2,%3}, {%4,%5,%6,%7}, {%8,%9}, {%0,%1,%2,%3};\n"
                        : "+f"(acc[m][n][0]), "+f"(acc[m][n][1]),
                          "+f"(acc[m][n][2]), "+f"(acc[m][n][3])
                        : "r"(afr[m][0]), "r"(afr[m][1]), "r"(afr[m][2]), "r"(afr[m][3]),
                          "r"(bfr[n][0]), "r"(bfr[n][1]));
                }
            }
        }
        __syncthreads();
    }

    // Epilogue: e = exp(sim * 10); skip diagonal element; partial row/col sums
    bool diag_tile = (bi == bj);
    float rsum[2][2];
    float csum[8][2];
    #pragma unroll
    for (int m = 0; m < 2; m++) { rsum[m][0] = 0.f; rsum[m][1] = 0.f; }
    #pragma unroll
    for (int n = 0; n < 8; n++) { csum[n][0] = 0.f; csum[n][1] = 0.f; }

    #pragma unroll
    for (int m = 0; m < 2; m++) {
        #pragma unroll
        for (int n = 0; n < 8; n++) {
            #pragma unroll
            for (int idx = 0; idx < 4; idx++) {
                int rl = wm + m * 16 + g + ((idx >> 1) << 3);
                int cl = wn + n * 8 + 2 * tg + (idx & 1);
                float e = __expf(acc[m][n][idx] * INV_TEMP);
                if (diag_tile && rl == cl) e = 0.f;
                rsum[m][idx >> 1] += e;
                csum[n][idx & 1]  += e;
            }
        }
    }

    // Row sums: reduce over tg (lane bits 0,1), one atomic per distinct row
    #pragma unroll
    for (int m = 0; m < 2; m++) {
        #pragma unroll
        for (int h = 0; h < 2; h++) {
            float v = rsum[m][h];
            v += __shfl_xor_sync(0xffffffffu, v, 1);
            v += __shfl_xor_sync(0xffffffffu, v, 2);
            if (tg == 0)
                atomicAdd(&g_rowsum[bi * 128 + wm + m * 16 + h * 8 + g], v);
        }
    }
    // Col sums (symmetric contribution) for strictly-upper tiles: reduce over g
    if (!diag_tile) {
        #pragma unroll
        for (int n = 0; n < 8; n++) {
            #pragma unroll
            for (int h = 0; h < 2; h++) {
                float v = csum[n][h];
                v += __shfl_xor_sync(0xffffffffu, v, 4);
                v += __shfl_xor_sync(0xffffffffu, v, 8);
                v += __shfl_xor_sync(0xffffffffu, v, 16);
                if (g == 0)
                    atomicAdd(&g_rowsum[bj * 128 + wn + n * 8 + 2 * tg + h], v);
            }
        }
    }
}

// ---------------------------------------------------------------------------
__global__ void final_kernel(float* __restrict__ out) {
    int t = threadIdx.x;
    float s = 0.f;
    for (int i = t; i < TWO_N; i += 256) s += logf(g_rowsum[i]);
    #pragma unroll
    for (int o = 16; o > 0; o >>= 1) s += __shfl_xor_sync(0xffffffffu, s, o);
    __shared__ float ws[8];
    int w = t >> 5;
    if ((t & 31) == 0) ws[w] = s;
    __syncthreads();
    if (t == 0) {
        float lse_sum = 0.f;
        #pragma unroll
        for (int i = 0; i < 8; i++) lse_sum += ws[i];
        // each positive dot appears twice (rows i and i+N), scaled by 1/temp
        float ssl = (lse_sum - 2.f * g_acc[0] * INV_TEMP) / (float)TWO_N;
        float invn = 1.0f / (float)N_ROWS;
        float sup = 1.0f * g_acc[1] * invn + 0.5f * g_acc[2] * invn + 0.3f * g_acc[3] * invn;
        out[0] = sup + 0.1f * ssl;
    }
}

// ---------------------------------------------------------------------------
extern "C" void kernel_launch(void* const* d_in, const int* in_sizes, int n_in,
                              void* d_out, int out_size) {
    const float* price_pred  = (const float*)d_in[0];
    const float* price_tgt   = (const float*)d_in[1];
    const float* change_pred = (const float*)d_in[2];
    const float* change_tgt  = (const float*)d_in[3];
    const float* crit_pred   = (const float*)d_in[4];
    const float* crit_tgt    = (const float*)d_in[5];
    const float* z1          = (const float*)d_in[6];
    const float* z2          = (const float*)d_in[7];

    init_kernel<<<TWO_N / 256, 256>>>();
    norm_kernel<<<N_ROWS, 256>>>(z1, z2);
    sup_kernel<<<N_ROWS / 256, 256>>>(price_pred, price_tgt, change_pred, change_tgt,
                                      crit_pred, crit_tgt);
    dim3 grid(NB, NB);
    gemm_exp_kernel<<<grid, 256>>>();
    final_kernel<<<1, 256>>>((float*)d_out);
}